// round 2
// baseline (speedup 1.0000x reference)
#include <cuda_runtime.h>

// Problem dims (fixed)
#define BB 8
#define SS 2048
#define DD 1024

// Scratch (__device__ globals — allowed; no runtime allocs)
__device__ float g_Q[(size_t)BB * SS * DD];
__device__ float g_K[(size_t)BB * SS * DD];
__device__ float g_V[(size_t)BB * SS * DD];
__device__ float g_S[(size_t)BB * SS * SS];

// ---------------- Tiled SGEMM: C = alpha * A(MxK) * B + bias ----------------
// TRANSB=false: B is [K,N] row-major.  TRANSB=true: B is [N,K] row-major (A*B^T).
// All of M, N multiples of 128; K multiple of 8 (and of 4 for float4 loads).
constexpr int BM = 128, BN = 128, BK = 8, TM = 8, TN = 8;

template <bool TRANSB, bool HAS_BIAS>
__global__ __launch_bounds__(256)
void sgemm_kernel(const float* __restrict__ A, const float* __restrict__ B,
                  const float* __restrict__ bias, float* __restrict__ C,
                  int M, int N, int K,
                  long long sA, long long sB, long long sC, float alpha)
{
    __shared__ float As[BK][BM];
    __shared__ float Bs[BK][BN];

    A += (long long)blockIdx.z * sA;
    B += (long long)blockIdx.z * sB;
    C += (long long)blockIdx.z * sC;

    const int rowBase = blockIdx.y * BM;
    const int colBase = blockIdx.x * BN;
    const int tid = threadIdx.x;
    const int tx = tid & 15;   // 0..15 -> col group
    const int ty = tid >> 4;   // 0..15 -> row group

    // A tile load indices: 128 rows x 8 k, float4 along k
    const int aRow = tid >> 1;
    const int aCol = (tid & 1) * 4;
    // B tile load indices
    const int bRowT = tid >> 1;         // TRANSB: n within tile
    const int bColT = (tid & 1) * 4;    // TRANSB: k4
    const int bRowN = tid >> 5;         // NN: k within tile
    const int bColN = (tid & 31) * 4;   // NN: n4

    float acc[TM][TN] = {};

    for (int k0 = 0; k0 < K; k0 += BK) {
        float4 a4 = *reinterpret_cast<const float4*>(
            A + (long long)(rowBase + aRow) * K + k0 + aCol);
        As[aCol + 0][aRow] = a4.x;
        As[aCol + 1][aRow] = a4.y;
        As[aCol + 2][aRow] = a4.z;
        As[aCol + 3][aRow] = a4.w;

        if (TRANSB) {
            float4 b4 = *reinterpret_cast<const float4*>(
                B + (long long)(colBase + bRowT) * K + k0 + bColT);
            Bs[bColT + 0][bRowT] = b4.x;
            Bs[bColT + 1][bRowT] = b4.y;
            Bs[bColT + 2][bRowT] = b4.z;
            Bs[bColT + 3][bRowT] = b4.w;
        } else {
            float4 b4 = *reinterpret_cast<const float4*>(
                B + (long long)(k0 + bRowN) * N + colBase + bColN);
            *reinterpret_cast<float4*>(&Bs[bRowN][bColN]) = b4;
        }
        __syncthreads();

        #pragma unroll
        for (int k = 0; k < BK; ++k) {
            float4 m0 = *reinterpret_cast<const float4*>(&As[k][ty * TM]);
            float4 m1 = *reinterpret_cast<const float4*>(&As[k][ty * TM + 4]);
            float4 n0 = *reinterpret_cast<const float4*>(&Bs[k][tx * TN]);
            float4 n1 = *reinterpret_cast<const float4*>(&Bs[k][tx * TN + 4]);
            float regM[TM] = {m0.x, m0.y, m0.z, m0.w, m1.x, m1.y, m1.z, m1.w};
            float regN[TN] = {n0.x, n0.y, n0.z, n0.w, n1.x, n1.y, n1.z, n1.w};
            #pragma unroll
            for (int i = 0; i < TM; ++i)
                #pragma unroll
                for (int j = 0; j < TN; ++j)
                    acc[i][j] += regM[i] * regN[j];
        }
        __syncthreads();
    }

    // Epilogue: alpha * acc (+ bias), float4 stores
    #pragma unroll
    for (int i = 0; i < TM; ++i) {
        const long long row = rowBase + ty * TM + i;
        #pragma unroll
        for (int j = 0; j < TN; j += 4) {
            const int col = colBase + tx * TN + j;
            float4 v;
            v.x = acc[i][j + 0] * alpha;
            v.y = acc[i][j + 1] * alpha;
            v.z = acc[i][j + 2] * alpha;
            v.w = acc[i][j + 3] * alpha;
            if (HAS_BIAS) {
                v.x += bias[col + 0];
                v.y += bias[col + 1];
                v.z += bias[col + 2];
                v.w += bias[col + 3];
            }
            *reinterpret_cast<float4*>(C + row * N + col) = v;
        }
    }
}

// ---------------- Row softmax over 2048 columns ----------------
__global__ __launch_bounds__(256)
void softmax2048_kernel(float* __restrict__ Sm)
{
    __shared__ float red[256];
    float* row = Sm + (long long)blockIdx.x * SS;
    const int tid = threadIdx.x;

    float v[8];
    float m = -1e30f;
    #pragma unroll
    for (int i = 0; i < 8; ++i) {
        v[i] = row[tid + 256 * i];
        m = fmaxf(m, v[i]);
    }
    red[tid] = m;
    __syncthreads();
    #pragma unroll
    for (int s = 128; s > 0; s >>= 1) {
        if (tid < s) red[tid] = fmaxf(red[tid], red[tid + s]);
        __syncthreads();
    }
    m = red[0];
    __syncthreads();

    float sum = 0.f;
    #pragma unroll
    for (int i = 0; i < 8; ++i) {
        v[i] = __expf(v[i] - m);
        sum += v[i];
    }
    red[tid] = sum;
    __syncthreads();
    #pragma unroll
    for (int s = 128; s > 0; s >>= 1) {
        if (tid < s) red[tid] += red[tid + s];
        __syncthreads();
    }
    const float inv = __frcp_rn(red[0]);
    #pragma unroll
    for (int i = 0; i < 8; ++i)
        row[tid + 256 * i] = v[i] * inv;
}

// ---------------- Launch ----------------
extern "C" void kernel_launch(void* const* d_in, const int* in_sizes, int n_in,
                              void* d_out, int out_size)
{
    const float* x  = (const float*)d_in[0];
    const float* Wq = (const float*)d_in[1];
    const float* bq = (const float*)d_in[2];
    const float* Wk = (const float*)d_in[3];
    const float* bk = (const float*)d_in[4];
    const float* Wv = (const float*)d_in[5];
    const float* bv = (const float*)d_in[6];
    float* out = (float*)d_out;

    float *Q, *K, *V, *Sc;
    cudaGetSymbolAddress((void**)&Q,  g_Q);
    cudaGetSymbolAddress((void**)&K,  g_K);
    cudaGetSymbolAddress((void**)&V,  g_V);
    cudaGetSymbolAddress((void**)&Sc, g_S);

    const int M = BB * SS;                 // 16384
    const long long strideQKV = (long long)SS * DD;  // 2M
    const long long strideS   = (long long)SS * SS;  // 4M
    dim3 blk(256);

    // 1) QKV projections: [16384,1024] x [1024,1024] + bias
    dim3 g1(DD / BN, M / BM, 1);
    sgemm_kernel<false, true><<<g1, blk>>>(x, Wq, bq, Q, M, DD, DD, 0, 0, 0, 1.f);
    sgemm_kernel<false, true><<<g1, blk>>>(x, Wk, bk, K, M, DD, DD, 0, 0, 0, 1.f);
    sgemm_kernel<false, true><<<g1, blk>>>(x, Wv, bv, V, M, DD, DD, 0, 0, 0, 1.f);

    // 2) Scores: per batch S_b = (Q_b * K_b^T) / 32   [2048 x 2048, K=1024]
    dim3 g2(SS / BN, SS / BM, BB);
    sgemm_kernel<true, false><<<g2, blk>>>(Q, K, nullptr, Sc, SS, SS, DD,
                                           strideQKV, strideQKV, strideS, 0.03125f);

    // 3) Softmax over last dim
    softmax2048_kernel<<<BB * SS, 256>>>(Sc);

    // 4) Output: per batch O_b = P_b * V_b   [2048 x 1024, K=2048]
    dim3 g3(DD / BN, SS / BM, BB);
    sgemm_kernel<false, false><<<g3, blk>>>(Sc, V, nullptr, out, SS, DD, SS,
                                            strideS, strideQKV, strideQKV, 1.f);
}

// round 4
// speedup vs baseline: 2.6902x; 2.6902x over previous
#include <cuda_runtime.h>
#include <cuda_bf16.h>
#include <cstdint>
#include <cstddef>

#define BB 8
#define SS 2048
#define DD 1024

typedef __nv_bfloat16 bf16;

// ---------------- scratch (__device__ globals; no runtime allocs) ----------------
__device__ bf16 g_xh[(size_t)BB * SS * DD];
__device__ bf16 g_xl[(size_t)BB * SS * DD];
__device__ bf16 g_Wth[(size_t)DD * DD];
__device__ bf16 g_Wtl[(size_t)DD * DD];
__device__ bf16 g_Qh[(size_t)BB * SS * DD];
__device__ bf16 g_Ql[(size_t)BB * SS * DD];
__device__ bf16 g_Kh[(size_t)BB * SS * DD];
__device__ bf16 g_Kl[(size_t)BB * SS * DD];
__device__ bf16 g_Vh[(size_t)BB * SS * DD];
__device__ bf16 g_Vl[(size_t)BB * SS * DD];
__device__ bf16 g_Vth[(size_t)BB * DD * SS];   // [b][d][s]
__device__ bf16 g_Vtl[(size_t)BB * DD * SS];
__device__ float g_S[(size_t)BB * SS * SS];
__device__ bf16 g_Ph[(size_t)BB * SS * SS];
__device__ bf16 g_Pl[(size_t)BB * SS * SS];

// ---------------- PTX helpers (sm_80-class only: cp.async / ldmatrix / mma.sync) ----
__device__ __forceinline__ uint32_t smem_u32(const void* p) {
    uint32_t a;
    asm("{ .reg .u64 t; cvta.to.shared.u64 t, %1; cvt.u32.u64 %0, t; }" : "=r"(a) : "l"(p));
    return a;
}
__device__ __forceinline__ void cp16(uint32_t s, const void* g) {
    asm volatile("cp.async.cg.shared.global [%0], [%1], 16;\n" :: "r"(s), "l"(g));
}
__device__ __forceinline__ void cp_commit() { asm volatile("cp.async.commit_group;\n" ::: "memory"); }
template <int N> __device__ __forceinline__ void cp_wait() {
    asm volatile("cp.async.wait_group %0;\n" :: "n"(N) : "memory");
}
__device__ __forceinline__ void ldsm_x4(uint32_t& r0, uint32_t& r1, uint32_t& r2, uint32_t& r3, uint32_t a) {
    asm volatile("ldmatrix.sync.aligned.m8n8.x4.shared.b16 {%0,%1,%2,%3}, [%4];"
                 : "=r"(r0), "=r"(r1), "=r"(r2), "=r"(r3) : "r"(a));
}
__device__ __forceinline__ void mma16816(float* d,
                                         uint32_t a0, uint32_t a1, uint32_t a2, uint32_t a3,
                                         uint32_t b0, uint32_t b1) {
    asm volatile("mma.sync.aligned.m16n8k16.row.col.f32.bf16.bf16.f32 "
                 "{%0,%1,%2,%3}, {%4,%5,%6,%7}, {%8,%9}, {%0,%1,%2,%3};"
                 : "+f"(d[0]), "+f"(d[1]), "+f"(d[2]), "+f"(d[3])
                 : "r"(a0), "r"(a1), "r"(a2), "r"(a3), "r"(b0), "r"(b1));
}

#define SW128(o) ((o) ^ (((o) >> 3) & 0x70))

// smem: 4 tensors x 128 rows x 64 bf16 (128B rows, SW128) per stage
static constexpr int S_AH = 0, S_AL = 16384, S_BH = 32768, S_BL = 49152;
static constexpr int STAGE = 65536;
static constexpr int STAGES = 3;
static constexpr int SMEM_TOTAL = STAGES * STAGE;   // 196608

// ---------------- split-bf16 tensor-core GEMM (mma.sync) ----------------
// C[M,N] = (Ah+Al)[M,K] x (Bh+Bl)[N,K]^T, fp32 accum, 3-pass compensated.
// CTA tile 128x128, K-chunk 64. EPI: 0 = fp32 out, 1 = bf16 hi/lo split out.
template <int EPI, bool HASB>
__global__ __launch_bounds__(256, 1)
void tc_gemm(const bf16* __restrict__ Ah_, const bf16* __restrict__ Al_,
             const bf16* __restrict__ Bh_, const bf16* __restrict__ Bl_,
             const float* __restrict__ bias,
             float* __restrict__ Co, bf16* __restrict__ Coh, bf16* __restrict__ Col,
             int Kd, long long sA, long long sB, long long sC, int ldo, float scale)
{
    extern __shared__ char smem[];
    const uint32_t su = smem_u32(smem);
    const int tid = threadIdx.x, lane = tid & 31, wid = tid >> 5;
    const int wm = wid >> 2, wn = wid & 3;              // warp grid 2(m) x 4(n)
    const int rowBase = blockIdx.y * 128, colBase = blockIdx.x * 128;

    Ah_ += (long long)blockIdx.z * sA;  Al_ += (long long)blockIdx.z * sA;
    Bh_ += (long long)blockIdx.z * sB;  Bl_ += (long long)blockIdx.z * sB;
    if (EPI == 0) Co += (long long)blockIdx.z * sC;
    else { Coh += (long long)blockIdx.z * sC; Col += (long long)blockIdx.z * sC; }

    float acc[16][4] = {};                               // [im*4+in][4]

    const int NC = Kd >> 6;

    auto load_stage = [&](int s, int k0) {
        const uint32_t base = su + s * STAGE;
        #pragma unroll
        for (int j = 0; j < 4; ++j) {
            const int idx = tid + j * 256, r = idx >> 3, cu = idx & 7;
            const size_t goA = (size_t)(rowBase + r) * Kd + k0 + cu * 8;
            const size_t goB = (size_t)(colBase + r) * Kd + k0 + cu * 8;
            const uint32_t so = SW128((uint32_t)(r * 128 + cu * 16));
            cp16(base + S_AH + so, Ah_ + goA);
            cp16(base + S_AL + so, Al_ + goA);
            cp16(base + S_BH + so, Bh_ + goB);
            cp16(base + S_BL + so, Bl_ + goB);
        }
        cp_commit();
    };

    load_stage(0, 0);
    load_stage(1, 64);

    // per-lane ldmatrix address components
    const uint32_t sw   = (lane & 7) << 4;               // SW128 xor (row&7)<<4
    const uint32_t arow = (lane & 7) + (lane & 8);       // row-in-16 pattern
    const uint32_t koff = (lane & 16);                   // +16B for k8..15 quadrant

    for (int c = 0; c < NC; ++c) {
        if (c + 2 < NC) load_stage((c + 2) % STAGES, (c + 2) << 6);
        else            cp_commit();                     // keep group counts aligned
        cp_wait<2>();
        __syncthreads();

        const uint32_t base = su + (c % STAGES) * STAGE;
        #pragma unroll
        for (int ks = 0; ks < 4; ++ks) {
            uint32_t ah[4][4], al[4][4];
            #pragma unroll
            for (int im = 0; im < 4; ++im) {
                const uint32_t off = (wm * 64 + im * 16 + arow) * 128 + ks * 32 + koff;
                ldsm_x4(ah[im][0], ah[im][1], ah[im][2], ah[im][3], (base + S_AH + off) ^ sw);
                ldsm_x4(al[im][0], al[im][1], al[im][2], al[im][3], (base + S_AL + off) ^ sw);
            }
            uint32_t bh[2][4], bl[2][4];
            #pragma unroll
            for (int ip = 0; ip < 2; ++ip) {
                const uint32_t off = (wn * 32 + ip * 16 + arow) * 128 + ks * 32 + koff;
                ldsm_x4(bh[ip][0], bh[ip][1], bh[ip][2], bh[ip][3], (base + S_BH + off) ^ sw);
                ldsm_x4(bl[ip][0], bl[ip][1], bl[ip][2], bl[ip][3], (base + S_BL + off) ^ sw);
            }
            #pragma unroll
            for (int im = 0; im < 4; ++im)
                #pragma unroll
                for (int in = 0; in < 4; ++in) {
                    float* d = acc[im * 4 + in];
                    const int ip = in >> 1, sb = in & 1;
                    const uint32_t b0h = bh[ip][sb], b1h = bh[ip][2 + sb];
                    const uint32_t b0l = bl[ip][sb], b1l = bl[ip][2 + sb];
                    mma16816(d, ah[im][0], ah[im][1], ah[im][2], ah[im][3], b0h, b1h);  // hi*hi
                    mma16816(d, al[im][0], al[im][1], al[im][2], al[im][3], b0h, b1h);  // lo*hi
                    mma16816(d, ah[im][0], ah[im][1], ah[im][2], ah[im][3], b0l, b1l);  // hi*lo
                }
        }
        __syncthreads();
    }

    // ---------------- epilogue ----------------
    #pragma unroll
    for (int im = 0; im < 4; ++im) {
        #pragma unroll
        for (int in = 0; in < 4; ++in) {
            const float* d = acc[im * 4 + in];
            const int row0 = rowBase + wm * 64 + im * 16 + (lane >> 2);
            const int col0 = colBase + wn * 32 + in * 8 + 2 * (lane & 3);
            #pragma unroll
            for (int h = 0; h < 2; ++h) {                // h=0: rows 0-7, h=1: rows 8-15
                const int row = row0 + h * 8;
                float v0 = d[2 * h + 0], v1 = d[2 * h + 1];
                if (HASB) { v0 += bias[col0]; v1 += bias[col0 + 1]; }
                v0 *= scale; v1 *= scale;
                if (EPI == 0) {
                    float2 f2; f2.x = v0; f2.y = v1;
                    *reinterpret_cast<float2*>(Co + (size_t)row * ldo + col0) = f2;
                } else {
                    const bf16 h0 = __float2bfloat16(v0), h1 = __float2bfloat16(v1);
                    __nv_bfloat162 H; H.x = h0; H.y = h1;
                    __nv_bfloat162 L;
                    L.x = __float2bfloat16(v0 - __bfloat162float(h0));
                    L.y = __float2bfloat16(v1 - __bfloat162float(h1));
                    *reinterpret_cast<__nv_bfloat162*>(Coh + (size_t)row * ldo + col0) = H;
                    *reinterpret_cast<__nv_bfloat162*>(Col + (size_t)row * ldo + col0) = L;
                }
            }
        }
    }
}

// ---------------- aux kernels ----------------
__global__ __launch_bounds__(256)
void split_x_kernel(const float4* __restrict__ src, bf16* __restrict__ hi, bf16* __restrict__ lo, int n4)
{
    const int i = blockIdx.x * 256 + threadIdx.x;
    if (i >= n4) return;
    const float4 v = src[i];
    bf16 h0 = __float2bfloat16(v.x), h1 = __float2bfloat16(v.y);
    bf16 h2 = __float2bfloat16(v.z), h3 = __float2bfloat16(v.w);
    __nv_bfloat162 H0; H0.x = h0; H0.y = h1;
    __nv_bfloat162 H1; H1.x = h2; H1.y = h3;
    __nv_bfloat162 L0, L1;
    L0.x = __float2bfloat16(v.x - __bfloat162float(h0));
    L0.y = __float2bfloat16(v.y - __bfloat162float(h1));
    L1.x = __float2bfloat16(v.z - __bfloat162float(h2));
    L1.y = __float2bfloat16(v.w - __bfloat162float(h3));
    reinterpret_cast<__nv_bfloat162*>(hi)[2 * i] = H0;
    reinterpret_cast<__nv_bfloat162*>(hi)[2 * i + 1] = H1;
    reinterpret_cast<__nv_bfloat162*>(lo)[2 * i] = L0;
    reinterpret_cast<__nv_bfloat162*>(lo)[2 * i + 1] = L1;
}

__global__ __launch_bounds__(256)
void transpose_split_w(const float* __restrict__ W, bf16* __restrict__ Th, bf16* __restrict__ Tl)
{
    __shared__ float t[32][33];
    const int tx = threadIdx.x, ty = threadIdx.y;
    const int x0 = blockIdx.x * 32, y0 = blockIdx.y * 32;
    #pragma unroll
    for (int j = 0; j < 32; j += 8)
        t[ty + j][tx] = W[(size_t)(y0 + ty + j) * DD + x0 + tx];
    __syncthreads();
    #pragma unroll
    for (int j = 0; j < 32; j += 8) {
        const float v = t[tx][ty + j];
        const size_t addr = (size_t)(x0 + ty + j) * DD + y0 + tx;
        const bf16 h = __float2bfloat16(v);
        Th[addr] = h;
        Tl[addr] = __float2bfloat16(v - __bfloat162float(h));
    }
}

// V[b][s][d] hi/lo -> Vt[b][d][s] hi/lo
__global__ __launch_bounds__(256)
void transpose_pair(const bf16* __restrict__ Vh, const bf16* __restrict__ Vl,
                    bf16* __restrict__ Vth, bf16* __restrict__ Vtl)
{
    __shared__ bf16 th[32][33], tl[32][33];
    const size_t bo = (size_t)blockIdx.z * SS * DD;
    const int tx = threadIdx.x, ty = threadIdx.y;
    const int d0 = blockIdx.x * 32, s0 = blockIdx.y * 32;
    #pragma unroll
    for (int j = 0; j < 32; j += 8) {
        th[ty + j][tx] = Vh[bo + (size_t)(s0 + ty + j) * DD + d0 + tx];
        tl[ty + j][tx] = Vl[bo + (size_t)(s0 + ty + j) * DD + d0 + tx];
    }
    __syncthreads();
    #pragma unroll
    for (int j = 0; j < 32; j += 8) {
        const size_t addr = bo + (size_t)(d0 + ty + j) * SS + s0 + tx;
        Vth[addr] = th[tx][ty + j];
        Vtl[addr] = tl[tx][ty + j];
    }
}

__global__ __launch_bounds__(256)
void softmax_split_kernel(const float* __restrict__ Sm, bf16* __restrict__ Ph, bf16* __restrict__ Pl)
{
    __shared__ float red[256];
    const float* row = Sm + (size_t)blockIdx.x * SS;
    bf16* oh = Ph + (size_t)blockIdx.x * SS;
    bf16* ol = Pl + (size_t)blockIdx.x * SS;
    const int tid = threadIdx.x;

    float v[8];
    float m = -1e30f;
    #pragma unroll
    for (int i = 0; i < 8; ++i) { v[i] = row[tid + 256 * i]; m = fmaxf(m, v[i]); }
    red[tid] = m; __syncthreads();
    #pragma unroll
    for (int s = 128; s > 0; s >>= 1) { if (tid < s) red[tid] = fmaxf(red[tid], red[tid + s]); __syncthreads(); }
    m = red[0]; __syncthreads();

    float sum = 0.f;
    #pragma unroll
    for (int i = 0; i < 8; ++i) { v[i] = __expf(v[i] - m); sum += v[i]; }
    red[tid] = sum; __syncthreads();
    #pragma unroll
    for (int s = 128; s > 0; s >>= 1) { if (tid < s) red[tid] += red[tid + s]; __syncthreads(); }
    const float inv = __frcp_rn(red[0]);
    #pragma unroll
    for (int i = 0; i < 8; ++i) {
        const float p = v[i] * inv;
        const bf16 h = __float2bfloat16(p);
        oh[tid + 256 * i] = h;
        ol[tid + 256 * i] = __float2bfloat16(p - __bfloat162float(h));
    }
}

// ---------------- launch ----------------
extern "C" void kernel_launch(void* const* d_in, const int* in_sizes, int n_in,
                              void* d_out, int out_size)
{
    const float* x  = (const float*)d_in[0];
    const float* Wq = (const float*)d_in[1];
    const float* bq = (const float*)d_in[2];
    const float* Wk = (const float*)d_in[3];
    const float* bk = (const float*)d_in[4];
    const float* Wv = (const float*)d_in[5];
    const float* bv = (const float*)d_in[6];
    float* out = (float*)d_out;

    bf16 *xh, *xl, *Wth, *Wtl, *Qh, *Ql, *Kh, *Kl, *Vh, *Vl, *Vth, *Vtl, *Ph, *Pl;
    float* Sc;
    cudaGetSymbolAddress((void**)&xh, g_xh);   cudaGetSymbolAddress((void**)&xl, g_xl);
    cudaGetSymbolAddress((void**)&Wth, g_Wth); cudaGetSymbolAddress((void**)&Wtl, g_Wtl);
    cudaGetSymbolAddress((void**)&Qh, g_Qh);   cudaGetSymbolAddress((void**)&Ql, g_Ql);
    cudaGetSymbolAddress((void**)&Kh, g_Kh);   cudaGetSymbolAddress((void**)&Kl, g_Kl);
    cudaGetSymbolAddress((void**)&Vh, g_Vh);   cudaGetSymbolAddress((void**)&Vl, g_Vl);
    cudaGetSymbolAddress((void**)&Vth, g_Vth); cudaGetSymbolAddress((void**)&Vtl, g_Vtl);
    cudaGetSymbolAddress((void**)&Sc, g_S);
    cudaGetSymbolAddress((void**)&Ph, g_Ph);   cudaGetSymbolAddress((void**)&Pl, g_Pl);

    cudaFuncSetAttribute(tc_gemm<0, false>, cudaFuncAttributeMaxDynamicSharedMemorySize, SMEM_TOTAL);
    cudaFuncSetAttribute(tc_gemm<1, true>,  cudaFuncAttributeMaxDynamicSharedMemorySize, SMEM_TOTAL);

    const long long sQKV = (long long)SS * DD;
    const long long sS   = (long long)SS * SS;

    // 0) split x into bf16 hi/lo
    split_x_kernel<<<(BB * SS * DD / 4 + 255) / 256, 256>>>((const float4*)x, xh, xl, BB * SS * DD / 4);

    dim3 tg(DD / 32, DD / 32), tb(32, 8);
    dim3 g1(DD / 128, BB * SS / 128, 1);     // (8, 128)
    dim3 g2(SS / 128, SS / 128, BB);         // (16, 16, 8)
    dim3 g3(DD / 128, SS / 128, BB);         // (8, 16, 8)

    // 1) Q = (x Wq + bq) / 32 -> split
    transpose_split_w<<<tg, tb>>>(Wq, Wth, Wtl);
    tc_gemm<1, true><<<g1, 256, SMEM_TOTAL>>>(xh, xl, Wth, Wtl, bq, nullptr, Qh, Ql,
                                              DD, 0, 0, 0, DD, 0.03125f);
    // 2) K = x Wk + bk -> split
    transpose_split_w<<<tg, tb>>>(Wk, Wth, Wtl);
    tc_gemm<1, true><<<g1, 256, SMEM_TOTAL>>>(xh, xl, Wth, Wtl, bk, nullptr, Kh, Kl,
                                              DD, 0, 0, 0, DD, 1.0f);
    // 3) V = x Wv + bv -> split, then transpose to [b][d][s]
    transpose_split_w<<<tg, tb>>>(Wv, Wth, Wtl);
    tc_gemm<1, true><<<g1, 256, SMEM_TOTAL>>>(xh, xl, Wth, Wtl, bv, nullptr, Vh, Vl,
                                              DD, 0, 0, 0, DD, 1.0f);
    transpose_pair<<<dim3(DD / 32, SS / 32, BB), tb>>>(Vh, Vl, Vth, Vtl);

    // 4) scores = Qs K^T (fp32)
    tc_gemm<0, false><<<g2, 256, SMEM_TOTAL>>>(Qh, Ql, Kh, Kl, nullptr, Sc, nullptr, nullptr,
                                               DD, sQKV, sQKV, sS, SS, 1.0f);
    // 5) softmax + split P
    softmax_split_kernel<<<BB * SS, 256>>>(Sc, Ph, Pl);
    // 6) out = P V   (A: P [q][s], B: Vt [d][s], both K-contiguous)
    tc_gemm<0, false><<<g3, 256, SMEM_TOTAL>>>(Ph, Pl, Vth, Vtl, nullptr, out, nullptr, nullptr,
                                               SS, sS, (long long)DD * SS, sQKV, DD, 1.0f);
}